// round 13
// baseline (speedup 1.0000x reference)
#include <cuda_runtime.h>

#define BB 64
#define TT 8000
#define SS 10
#define CHUNKS 8
#define ROWSPC (TT / CHUNKS)                  // 1000 rows per chunk
#define NTILE 4
#define TROWS 250                             // rows per tile
#define TFLOATS (TROWS * SS)                  // 2500 floats per tile per array
#define TF4 (TFLOATS / 4)                     // 625 float4 per tile per array
#define NACC 110                              // 100 sel + 10 tot
#define FULL 0xFFFFFFFFu
#define FLT_MAX_C 3.402823466e+38f
#define LN2F 0.69314718055994530942f

// Scratch (no allocations allowed). Zero-initialized device globals.
__device__ float    g_part[BB * CHUNKS * NACC];
__device__ double   g_bsum[BB];
__device__ unsigned g_ticket2;

typedef unsigned long long u64;

__device__ __forceinline__ unsigned enc_f32(float x) {
    unsigned b = __float_as_uint(x);
    return (b & 0x80000000u) ? ~b : (b | 0x80000000u);
}
__device__ __forceinline__ float dec_f32(unsigned e) {
    unsigned b = (e & 0x80000000u) ? (e & 0x7FFFFFFFu) : ~e;
    return __uint_as_float(b);
}

// 10-way register select, 4-deep tree (idx in 0..9).
__device__ __forceinline__ float sel10(const float w[SS], int idx) {
    const float x01 = (idx & 1) ? w[1] : w[0];
    const float x23 = (idx & 1) ? w[3] : w[2];
    const float x45 = (idx & 1) ? w[5] : w[4];
    const float x67 = (idx & 1) ? w[7] : w[6];
    const float x89 = (idx & 1) ? w[9] : w[8];
    const float y03 = (idx & 2) ? x23 : x01;
    const float y47 = (idx & 2) ? x67 : x45;
    const float z07 = (idx & 4) ? y47 : y03;
    return (idx & 8) ? x89 : z07;
}

__device__ __forceinline__ int nib_get(u64 x, int i) {
    return (int)((x >> (i * 4)) & 15ull);
}
__device__ __forceinline__ u64 nib_set(u64 x, int i, int val) {
    const int s = i * 4;
    return (x & ~(15ull << s)) | ((u64)val << s);
}

// ---------------------------------------------------------------------------
// Kernel 1: smem-staged pairwise BCE partial reduction.
// 512 blocks x 256 threads, 4 blocks/SM, one wave. Per 250-row tile:
//   stage : float4-coalesced GMEM -> smem (double buffered)
//   phaseA: 250 threads (column-stable i = tid/25) transform p -> diff in
//           place (2 MUFU per element, computed ONCE) and accumulate tot[i]
//   phaseB: 4 warp classes (ihalf, jhalf) accumulate sel[5][5] from smem
// ---------------------------------------------------------------------------
__global__ __launch_bounds__(256, 4) void pairwise_kernel(const float* __restrict__ pred,
                                                          const float* __restrict__ tgt) {
    __shared__ float bp[2][TFLOATS];
    __shared__ float bt[2][TFLOATS];
    __shared__ float s_totp[256];
    __shared__ float s_sel[8][25];

    const int b    = blockIdx.x / CHUNKS;
    const int c    = blockIdx.x % CHUNKS;
    const int tid  = threadIdx.x;
    const int lane = tid & 31;
    const int w    = tid >> 5;
    const int q    = w >> 1;                  // warp class: IH = q&1, JH = q>>1
    const int IH   = q & 1;
    const int JH   = q >> 1;
    const int slot = tid & 63;

    const float* pg = pred + (size_t)(b * TT + c * ROWSPC) * SS;
    const float* tg = tgt  + (size_t)(b * TT + c * ROWSPC) * SS;

    // Phase-A ownership: thread tid<250 owns column i_pa, rows r0_pa+25m.
    const int i_pa  = tid / 25;               // 0..10 (>=10 -> inactive)
    const int r0_pa = tid % 25;
    const bool paAct = (tid < 250);

    float tot = 0.0f;                         // per-thread tot partial (fixed i)
    float sel[5][5];
#pragma unroll
    for (int ii = 0; ii < 5; ii++)
#pragma unroll
        for (int jj = 0; jj < 5; jj++) sel[ii][jj] = 0.0f;

    for (int k = 0; k < NTILE; k++) {
        const int cur = k & 1;
        // ---- stage tile k (float4 coalesced; buffer cur free by sync logic) ----
        {
            const float4* pg4 = reinterpret_cast<const float4*>(pg + k * TFLOATS);
            const float4* tg4 = reinterpret_cast<const float4*>(tg + k * TFLOATS);
            float4* bp4 = reinterpret_cast<float4*>(bp[cur]);
            float4* bt4 = reinterpret_cast<float4*>(bt[cur]);
            for (int u = tid; u < TF4; u += 256) {
                bp4[u] = pg4[u];
                bt4[u] = tg4[u];
            }
        }
        __syncthreads();

        // ---- phase A: p -> diff in place, tot accumulate (each element once) ----
        if (paAct) {
#pragma unroll
            for (int m = 0; m < 10; m++) {
                const int e = (r0_pa + 25 * m) * SS + i_pa;
                const float p  = bp[cur][e];
                const float l1 = __log2f(p);
                const float l2 = __log2f(1.0f - p);
                bp[cur][e] = l1 - l2;          // diff, lg2 units
                tot += l2;
            }
        }
        __syncthreads();

        // ---- phase B: class accumulation from smem ----
#pragma unroll
        for (int m = 0; m < 4; m++) {
            const int r = slot + 64 * m;
            if (r < TROWS) {
                const float2* dw = reinterpret_cast<const float2*>(&bp[cur][r * SS + IH * 4]);
                const float2* tw = reinterpret_cast<const float2*>(&bt[cur][r * SS + JH * 4]);
                const float2 d0 = dw[0], d1 = dw[1], d2 = dw[2];
                const float2 t0 = tw[0], t1 = tw[1], t2 = tw[2];
                const float de[6] = {d0.x, d0.y, d1.x, d1.y, d2.x, d2.y};
                const float te[6] = {t0.x, t0.y, t1.x, t1.y, t2.x, t2.y};
#pragma unroll
                for (int jj = 0; jj < 5; jj++) {
                    const float tj = te[jj + JH];      // exactly 0.0f or 1.0f
#pragma unroll
                    for (int ii = 0; ii < 5; ii++)
                        sel[ii][jj] = fmaf(de[ii + IH], tj, sel[ii][jj]);
                }
            }
        }
        // Loop-top sync (after next stage) protects buffers; need one sync here
        // so the next stage (writing buf (k+1)&1) can't race phase B of k-1...
        // guaranteed by the two syncs per iteration (see analysis).
    }
    __syncthreads();

    // ---- reductions ----
    s_totp[tid] = paAct ? tot : 0.0f;

    // Full-warp tree reduction of the 25 sel accumulators -> lane 0.
#pragma unroll
    for (int ii = 0; ii < 5; ii++) {
#pragma unroll
        for (int jj = 0; jj < 5; jj++) {
            float v = sel[ii][jj];
#pragma unroll
            for (int o = 16; o; o >>= 1) v += __shfl_down_sync(FULL, v, o);
            sel[ii][jj] = v;
        }
    }
    if (lane == 0) {
#pragma unroll
        for (int ii = 0; ii < 5; ii++)
#pragma unroll
            for (int jj = 0; jj < 5; jj++) s_sel[w][ii * 5 + jj] = sel[ii][jj];
    }
    __syncthreads();

    if (tid < 100) {
        const int i = tid / 10, j = tid % 10;
        const int ih = (i >= 5), jh = (j >= 5);
        const int qq  = jh * 2 + ih;
        const int idx = (i % 5) * 5 + (j % 5);
        g_part[(b * CHUNKS + c) * NACC + tid] =
            (s_sel[2 * qq][idx] + s_sel[2 * qq + 1][idx]) * LN2F;
    } else if (tid < 100 + SS) {
        const int i = tid - 100;
        float v = 0.0f;
#pragma unroll
        for (int kk = 0; kk < 25; kk++) v += s_totp[i * 25 + kk];
        g_part[(b * CHUNKS + c) * NACC + tid] = v * LN2F;
    }
}

// ---------------------------------------------------------------------------
// Kernel 2: warp-per-batch Hungarian (r10 frozen: JV, warm start + greedy,
// one REDUX per Dijkstra iteration, uniform nibble-packed p64) + fused mean.
// ---------------------------------------------------------------------------
__global__ __launch_bounds__(128) void hungarian_kernel(float* __restrict__ out) {
    __shared__ float s_cost[100];
    const int b   = blockIdx.x;
    const int tid = threadIdx.x;
    const int lane = tid & 31;

    if (tid < 100) {
        const int i = tid / 10;
        float sl = 0.0f, to = 0.0f;
#pragma unroll
        for (int c = 0; c < CHUNKS; c++) {
            const float* gp = &g_part[(b * CHUNKS + c) * NACC];
            sl += __ldcg(&gp[tid]);
            to += __ldcg(&gp[100 + i]);
        }
        s_cost[tid] = -(to + sl) * (1.0f / (float)TT);
    }
    __syncthreads();
    if (tid >= 32) return;

    const bool isCol = (lane >= 1 && lane <= SS);
    const int  cl    = isCol ? (lane - 1) : 0;

    float colv[SS];
#pragma unroll
    for (int i = 0; i < SS; i++) colv[i] = s_cost[i * 10 + cl];

    // Warm start: v[j] = min_i colv (lane); u[i] = min_j (colv[i]-v) (uniform).
    float v = 0.0f;
    if (isCol) {
        float mn = colv[0];
#pragma unroll
        for (int i = 1; i < SS; i++) mn = fminf(mn, colv[i]);
        v = mn;
    }
    float uu[SS];
#pragma unroll
    for (int i = 0; i < SS; i++) {
        const float t = isCol ? (colv[i] - v) : FLT_MAX_C;
        uu[i] = dec_f32(__reduce_min_sync(FULL, enc_f32(t)));   // exact (full key)
    }

    // Greedy tight-edge pre-assignment (p64 kept uniform in all lanes).
    u64 p64 = 0ull;
    int way = 0;                       // lane j: alternating-path parent
    unsigned rowdone = 0u;
#pragma unroll
    for (int i = 1; i <= SS; i++) {
        const float red = isCol ? ((colv[i - 1] - v) - uu[i - 1]) : 1.0f;
        const bool  z   = isCol && (nib_get(p64, lane) == 0) && (red == 0.0f);
        const unsigned bal = __ballot_sync(FULL, z);
        if (bal) {
            const int j = __ffs(bal) - 1;
            p64 = nib_set(p64, j, i);                   // uniform update
            rowdone |= 1u << i;
        }
    }

    // Dijkstra per remaining free row: ONE collective (REDUX.MIN) per iter.
    for (int root = 1; root <= SS; root++) {
        if ((rowdone >> root) & 1u) continue;
        p64 = nib_set(p64, 0, root);                    // p[0] = root

        float wv[SS];
#pragma unroll
        for (int i = 0; i < SS; i++)
            wv[i] = isCol ? ((colv[i] - uu[i]) - v) : FLT_MAX_C;

        float minv = FLT_MAX_C;
        unsigned used = 1u;            // virtual column 0
        unsigned rowm = 0u;
        int j0 = 0, i0 = root;

        while (true) {
            rowm |= 1u << i0;

            const bool  active = isCol && !((used >> lane) & 1u);
            const float cur    = sel10(wv, i0 - 1);
            if (active && cur < minv) { minv = cur; way = j0; }

            const unsigned key = active ? ((enc_f32(minv) & 0xFFFFFFE0u) | (unsigned)lane)
                                        : 0xFFFFFFFFu;
            const unsigned m   = __reduce_min_sync(FULL, key);
            const int      j1  = (int)(m & 31u);
            const float delta  = dec_f32(m & 0xFFFFFFE0u);  // <=exact by <32ulp; feasible
            const int   pn     = nib_get(p64, j1);          // uniform ALU, no shfl

            if (lane <= SS) {
                if ((used >> lane) & 1u) v -= delta;
                else                     minv -= delta;
            }
#pragma unroll
            for (int i = 1; i <= SS; i++)
                if ((rowm >> i) & 1u) uu[i - 1] += delta;   // uniform

            used |= 1u << j1;
            j0 = j1;
            if (pn == 0) break;
            i0 = pn;
        }

        // Augment along the alternating path (p64 stays uniform).
        while (j0) {
            const int jprev = __shfl_sync(FULL, way, j0);
            p64 = nib_set(p64, j0, nib_get(p64, jprev));
            j0 = jprev;
        }
    }

    // Matched sum (exact f32 cost entries, f64 accumulate).
    double val = 0.0;
    if (isCol) val = (double)s_cost[(nib_get(p64, lane) - 1) * 10 + cl];
#pragma unroll
    for (int o = 16; o; o >>= 1) val += __shfl_down_sync(FULL, val, o);
    if (lane == 0) g_bsum[b] = val;

    // Fused finalize: last block computes the mean.
    __threadfence();
    unsigned t2 = 0;
    if (lane == 0) t2 = atomicAdd(&g_ticket2, 1u);
    t2 = __shfl_sync(FULL, t2, 0);
    if (t2 == BB - 1) {
        if (lane == 0) g_ticket2 = 0;              // reset for graph replay
        __threadfence();
        double x = __ldcg(&g_bsum[lane]) + __ldcg(&g_bsum[lane + 32]);
#pragma unroll
        for (int o = 16; o; o >>= 1) x += __shfl_down_sync(FULL, x, o);
        if (lane == 0) out[0] = (float)(x / (double)(BB * SS));
    }
}

extern "C" void kernel_launch(void* const* d_in, const int* in_sizes, int n_in,
                              void* d_out, int out_size) {
    const float* pred = (const float*)d_in[0];
    const float* tgt  = (const float*)d_in[1];
    pairwise_kernel<<<BB * CHUNKS, 256>>>(pred, tgt);
    hungarian_kernel<<<BB, 128>>>((float*)d_out);
}

// round 14
// speedup vs baseline: 1.5158x; 1.5158x over previous
#include <cuda_runtime.h>

#define BB 64
#define TT 8000
#define SS 10
#define CHUNKS 8
#define ROWSPC (TT / CHUNKS)                  // 1000 rows per block
#define NTILE 4
#define TROWS 250                             // rows per tile
#define TPAD 251                              // smem column stride (bank spread)
#define TF4 ((TROWS * SS) / 4)                // 625 float4 per tile per array
#define NACC 110                              // 100 sel + 10 tot
#define FULL 0xFFFFFFFFu
#define FLT_MAX_C 3.402823466e+38f
#define LN2F 0.69314718055994530942f

// Scratch (no allocations allowed). Zero-initialized device globals.
__device__ float    g_part[BB * CHUNKS * NACC];
__device__ double   g_bsum[BB];
__device__ unsigned g_ticket2;

typedef unsigned long long u64;

__device__ __forceinline__ unsigned enc_f32(float x) {
    unsigned b = __float_as_uint(x);
    return (b & 0x80000000u) ? ~b : (b | 0x80000000u);
}
__device__ __forceinline__ float dec_f32(unsigned e) {
    unsigned b = (e & 0x80000000u) ? (e & 0x7FFFFFFFu) : ~e;
    return __uint_as_float(b);
}

// 10-way register select, 4-deep tree (idx in 0..9).
__device__ __forceinline__ float sel10(const float w[SS], int idx) {
    const float x01 = (idx & 1) ? w[1] : w[0];
    const float x23 = (idx & 1) ? w[3] : w[2];
    const float x45 = (idx & 1) ? w[5] : w[4];
    const float x67 = (idx & 1) ? w[7] : w[6];
    const float x89 = (idx & 1) ? w[9] : w[8];
    const float y03 = (idx & 2) ? x23 : x01;
    const float y47 = (idx & 2) ? x67 : x45;
    const float z07 = (idx & 4) ? y47 : y03;
    return (idx & 8) ? x89 : z07;
}

__device__ __forceinline__ int nib_get(u64 x, int i) {
    return (int)((x >> (i * 4)) & 15ull);
}
__device__ __forceinline__ u64 nib_set(u64 x, int i, int val) {
    const int s = i * 4;
    return (x & ~(15ull << s)) | ((u64)val << s);
}

// ---------------------------------------------------------------------------
// Kernel 1: pairwise BCE with coalesced staging + transposed smem.
// 512 blocks x 256 threads, 4 blocks/SM, one wave. Per 250-row tile:
//   stage : float4-coalesced LDG; logs computed inline (once per element);
//           diff/l2/tgt written COLUMN-MAJOR to smem (stride 251).
//   accum : 4 warp classes (IH, JH) read conflict-free LDS.32 columns and
//           accumulate sel[5][5]; threads 0..49 accumulate tot from l2.
// ---------------------------------------------------------------------------
__global__ __launch_bounds__(256, 4) void pairwise_kernel(const float* __restrict__ pred,
                                                          const float* __restrict__ tgt) {
    __shared__ float sd[SS * TPAD];   // diff (lg2 units), column-major
    __shared__ float sl[SS * TPAD];   // lg2(1-p), column-major
    __shared__ float st[SS * TPAD];   // targets, column-major
    __shared__ float s_sel[8][25];
    __shared__ float s_totp[50];

    const int b    = blockIdx.x / CHUNKS;
    const int c    = blockIdx.x % CHUNKS;
    const int tid  = threadIdx.x;
    const int lane = tid & 31;
    const int w    = tid >> 5;
    const int q    = w >> 1;                  // warp class
    const int IH   = q & 1;
    const int JH   = q >> 1;
    const int slot = tid & 63;

    const float* pg = pred + (size_t)(b * TT + c * ROWSPC) * SS;
    const float* tg = tgt  + (size_t)(b * TT + c * ROWSPC) * SS;

    const int  i_t   = tid % 10;              // tot ownership (tid < 50)
    const int  q_t   = tid / 10;
    const bool totAct = (tid < 50);

    float sel[5][5];
#pragma unroll
    for (int ii = 0; ii < 5; ii++)
#pragma unroll
        for (int jj = 0; jj < 5; jj++) sel[ii][jj] = 0.0f;
    float totp = 0.0f;

    for (int k = 0; k < NTILE; k++) {
        // ---- stage pred (+ inline logs) and tgt, transposed ----
        {
            const float4* pg4 = reinterpret_cast<const float4*>(pg + k * TROWS * SS);
            const float4* tg4 = reinterpret_cast<const float4*>(tg + k * TROWS * SS);
            for (int u = tid; u < TF4; u += 256) {
                const float4 vp = pg4[u];
                const float4 vt = tg4[u];
                const int e0 = 4 * u;
                int r   = e0 / 10;
                int col = e0 - 10 * r;
                const float pv[4] = {vp.x, vp.y, vp.z, vp.w};
                const float tv[4] = {vt.x, vt.y, vt.z, vt.w};
#pragma unroll
                for (int e = 0; e < 4; e++) {
                    const float p  = pv[e];
                    const float l1 = __log2f(p);           // lg2(p)
                    const float l2 = __log2f(1.0f - p);    // lg2(1-p)
                    const int   a  = col * TPAD + r;
                    sd[a] = l1 - l2;
                    sl[a] = l2;
                    st[a] = tv[e];
                    if (++col == 10) { col = 0; ++r; }
                }
            }
        }
        __syncthreads();

        // ---- class accumulation: conflict-free column reads ----
#pragma unroll
        for (int m = 0; m < 4; m++) {
            const int r = slot + 64 * m;
            if (r < TROWS) {
                float de[5], te[5];
#pragma unroll
                for (int ii = 0; ii < 5; ii++) de[ii] = sd[(IH * 5 + ii) * TPAD + r];
#pragma unroll
                for (int jj = 0; jj < 5; jj++) te[jj] = st[(JH * 5 + jj) * TPAD + r];
#pragma unroll
                for (int jj = 0; jj < 5; jj++)
#pragma unroll
                    for (int ii = 0; ii < 5; ii++)
                        sel[ii][jj] = fmaf(de[ii], te[jj], sel[ii][jj]);
            }
        }

        // ---- tot accumulation: thread (i, quarter) sums 50 l2 values ----
        if (totAct) {
            const float* col = &sl[i_t * TPAD + q_t * 50];
#pragma unroll
            for (int rr = 0; rr < 50; rr++) totp += col[rr];
        }
        __syncthreads();
    }

    // ---- reductions ----
#pragma unroll
    for (int ii = 0; ii < 5; ii++)
#pragma unroll
        for (int jj = 0; jj < 5; jj++) {
            float v = sel[ii][jj];
#pragma unroll
            for (int o = 16; o; o >>= 1) v += __shfl_down_sync(FULL, v, o);
            sel[ii][jj] = v;
        }
    if (lane == 0) {
#pragma unroll
        for (int ii = 0; ii < 5; ii++)
#pragma unroll
            for (int jj = 0; jj < 5; jj++) s_sel[w][ii * 5 + jj] = sel[ii][jj];
    }
    if (totAct) s_totp[tid] = totp;
    __syncthreads();

    if (tid < 100) {
        const int i = tid / 10, j = tid % 10;
        const int ih = (i >= 5), jh = (j >= 5);
        const int qq  = jh * 2 + ih;
        const int idx = (i % 5) * 5 + (j % 5);
        g_part[(b * CHUNKS + c) * NACC + tid] =
            (s_sel[2 * qq][idx] + s_sel[2 * qq + 1][idx]) * LN2F;
    } else if (tid < 100 + SS) {
        const int i = tid - 100;
        float v = 0.0f;
#pragma unroll
        for (int qq = 0; qq < 5; qq++) v += s_totp[qq * 10 + i];
        g_part[(b * CHUNKS + c) * NACC + tid] = v * LN2F;
    }
}

// ---------------------------------------------------------------------------
// Kernel 2: warp-per-batch Hungarian (r10 frozen: JV, warm start + greedy,
// one REDUX per Dijkstra iteration, uniform nibble-packed p64) + fused mean.
// ---------------------------------------------------------------------------
__global__ __launch_bounds__(128) void hungarian_kernel(float* __restrict__ out) {
    __shared__ float s_cost[100];
    const int b   = blockIdx.x;
    const int tid = threadIdx.x;
    const int lane = tid & 31;

    if (tid < 100) {
        const int i = tid / 10;
        float sl = 0.0f, to = 0.0f;
#pragma unroll
        for (int c = 0; c < CHUNKS; c++) {
            const float* gp = &g_part[(b * CHUNKS + c) * NACC];
            sl += __ldcg(&gp[tid]);
            to += __ldcg(&gp[100 + i]);
        }
        s_cost[tid] = -(to + sl) * (1.0f / (float)TT);
    }
    __syncthreads();
    if (tid >= 32) return;

    const bool isCol = (lane >= 1 && lane <= SS);
    const int  cl    = isCol ? (lane - 1) : 0;

    float colv[SS];
#pragma unroll
    for (int i = 0; i < SS; i++) colv[i] = s_cost[i * 10 + cl];

    // Warm start: v[j] = min_i colv (lane); u[i] = min_j (colv[i]-v) (uniform).
    float v = 0.0f;
    if (isCol) {
        float mn = colv[0];
#pragma unroll
        for (int i = 1; i < SS; i++) mn = fminf(mn, colv[i]);
        v = mn;
    }
    float uu[SS];
#pragma unroll
    for (int i = 0; i < SS; i++) {
        const float t = isCol ? (colv[i] - v) : FLT_MAX_C;
        uu[i] = dec_f32(__reduce_min_sync(FULL, enc_f32(t)));   // exact (full key)
    }

    // Greedy tight-edge pre-assignment (p64 kept uniform in all lanes).
    u64 p64 = 0ull;
    int way = 0;                       // lane j: alternating-path parent
    unsigned rowdone = 0u;
#pragma unroll
    for (int i = 1; i <= SS; i++) {
        const float red = isCol ? ((colv[i - 1] - v) - uu[i - 1]) : 1.0f;
        const bool  z   = isCol && (nib_get(p64, lane) == 0) && (red == 0.0f);
        const unsigned bal = __ballot_sync(FULL, z);
        if (bal) {
            const int j = __ffs(bal) - 1;
            p64 = nib_set(p64, j, i);                   // uniform update
            rowdone |= 1u << i;
        }
    }

    // Dijkstra per remaining free row: ONE collective (REDUX.MIN) per iter.
    for (int root = 1; root <= SS; root++) {
        if ((rowdone >> root) & 1u) continue;
        p64 = nib_set(p64, 0, root);                    // p[0] = root

        float wv[SS];
#pragma unroll
        for (int i = 0; i < SS; i++)
            wv[i] = isCol ? ((colv[i] - uu[i]) - v) : FLT_MAX_C;

        float minv = FLT_MAX_C;
        unsigned used = 1u;            // virtual column 0
        unsigned rowm = 0u;
        int j0 = 0, i0 = root;

        while (true) {
            rowm |= 1u << i0;

            const bool  active = isCol && !((used >> lane) & 1u);
            const float cur    = sel10(wv, i0 - 1);
            if (active && cur < minv) { minv = cur; way = j0; }

            const unsigned key = active ? ((enc_f32(minv) & 0xFFFFFFE0u) | (unsigned)lane)
                                        : 0xFFFFFFFFu;
            const unsigned m   = __reduce_min_sync(FULL, key);
            const int      j1  = (int)(m & 31u);
            const float delta  = dec_f32(m & 0xFFFFFFE0u);  // <=exact by <32ulp; feasible
            const int   pn     = nib_get(p64, j1);          // uniform ALU, no shfl

            if (lane <= SS) {
                if ((used >> lane) & 1u) v -= delta;
                else                     minv -= delta;
            }
#pragma unroll
            for (int i = 1; i <= SS; i++)
                if ((rowm >> i) & 1u) uu[i - 1] += delta;   // uniform

            used |= 1u << j1;
            j0 = j1;
            if (pn == 0) break;
            i0 = pn;
        }

        // Augment along the alternating path (p64 stays uniform).
        while (j0) {
            const int jprev = __shfl_sync(FULL, way, j0);
            p64 = nib_set(p64, j0, nib_get(p64, jprev));
            j0 = jprev;
        }
    }

    // Matched sum (exact f32 cost entries, f64 accumulate).
    double val = 0.0;
    if (isCol) val = (double)s_cost[(nib_get(p64, lane) - 1) * 10 + cl];
#pragma unroll
    for (int o = 16; o; o >>= 1) val += __shfl_down_sync(FULL, val, o);
    if (lane == 0) g_bsum[b] = val;

    // Fused finalize: last block computes the mean.
    __threadfence();
    unsigned t2 = 0;
    if (lane == 0) t2 = atomicAdd(&g_ticket2, 1u);
    t2 = __shfl_sync(FULL, t2, 0);
    if (t2 == BB - 1) {
        if (lane == 0) g_ticket2 = 0;              // reset for graph replay
        __threadfence();
        double x = __ldcg(&g_bsum[lane]) + __ldcg(&g_bsum[lane + 32]);
#pragma unroll
        for (int o = 16; o; o >>= 1) x += __shfl_down_sync(FULL, x, o);
        if (lane == 0) out[0] = (float)(x / (double)(BB * SS));
    }
}

extern "C" void kernel_launch(void* const* d_in, const int* in_sizes, int n_in,
                              void* d_out, int out_size) {
    const float* pred = (const float*)d_in[0];
    const float* tgt  = (const float*)d_in[1];
    pairwise_kernel<<<BB * CHUNKS, 256>>>(pred, tgt);
    hungarian_kernel<<<BB, 128>>>((float*)d_out);
}

// round 15
// speedup vs baseline: 1.6531x; 1.0906x over previous
#include <cuda_runtime.h>

#define BB 64
#define TT 8000
#define SS 10
#define CHUNKS 9
#define ROWSPC ((TT + CHUNKS - 1) / CHUNKS)   // 889
#define NACC 110                              // 100 sel + 10 tot
#define FULL 0xFFFFFFFFu
#define FLT_MAX_C 3.402823466e+38f
#define LN2F 0.69314718055994530942f

// Scratch (no allocations allowed). Zero-initialized device globals.
__device__ float    g_part[BB * CHUNKS * NACC];
__device__ double   g_bsum[BB];
__device__ unsigned g_ticket2;

typedef unsigned long long u64;

__device__ __forceinline__ unsigned enc_f32(float x) {
    unsigned b = __float_as_uint(x);
    return (b & 0x80000000u) ? ~b : (b | 0x80000000u);
}
__device__ __forceinline__ float dec_f32(unsigned e) {
    unsigned b = (e & 0x80000000u) ? (e & 0x7FFFFFFFu) : ~e;
    return __uint_as_float(b);
}

// 10-way register select, 4-deep tree (idx in 0..9).
__device__ __forceinline__ float sel10(const float w[SS], int idx) {
    const float x01 = (idx & 1) ? w[1] : w[0];
    const float x23 = (idx & 1) ? w[3] : w[2];
    const float x45 = (idx & 1) ? w[5] : w[4];
    const float x67 = (idx & 1) ? w[7] : w[6];
    const float x89 = (idx & 1) ? w[9] : w[8];
    const float y03 = (idx & 2) ? x23 : x01;
    const float y47 = (idx & 2) ? x67 : x45;
    const float z07 = (idx & 4) ? y47 : y03;
    return (idx & 8) ? x89 : z07;
}

__device__ __forceinline__ int nib_get(u64 x, int i) {
    return (int)((x >> (i * 4)) & 15ull);
}
__device__ __forceinline__ u64 nib_set(u64 x, int i, int val) {
    const int s = i * 4;
    return (x & ~(15ull << s)) | ((u64)val << s);
}

// ---------------------------------------------------------------------------
// Kernel 1: pairwise BCE partial reduction — FROZEN r6 config (proven 12.5us).
// 576 blocks x 256 threads, 4 blocks/SM. Warp class (ihalf, jhalf) owns a
// 5x5 tile of the 10x10 outer product; lg2 accumulation, x ln2 once.
// ---------------------------------------------------------------------------
template <int IH, int JH>
__device__ __forceinline__ void pw_body(const float* __restrict__ pred,
                                        const float* __restrict__ tgt,
                                        int b, int t0, int tend, int slot,
                                        float sel[5][5], float tot[5]) {
    for (int t = t0 + slot; t < tend; t += 64) {
        const size_t base = ((size_t)b * TT + (size_t)t) * SS;
        const float2* pp = reinterpret_cast<const float2*>(pred + base + IH * 4);
        const float2* tp = reinterpret_cast<const float2*>(tgt  + base + JH * 4);
        const float2 p0 = pp[0], p1 = pp[1], p2 = pp[2];
        const float2 q0 = tp[0], q1 = tp[1], q2 = tp[2];
        const float pe[6] = {p0.x, p0.y, p1.x, p1.y, p2.x, p2.y};
        const float te[6] = {q0.x, q0.y, q1.x, q1.y, q2.x, q2.y};

        float diff[5];
#pragma unroll
        for (int ii = 0; ii < 5; ii++) {
            const float p  = pe[ii + IH];          // static index
            const float l1 = __log2f(p);           // lg2(p)
            const float l2 = __log2f(1.0f - p);    // lg2(1-p); p in [0.01, 0.99]
            diff[ii] = l1 - l2;
            tot[ii] += l2;
        }
#pragma unroll
        for (int jj = 0; jj < 5; jj++) {
            const float tj = te[jj + JH];          // exactly 0.0f or 1.0f
#pragma unroll
            for (int ii = 0; ii < 5; ii++)
                sel[ii][jj] = fmaf(diff[ii], tj, sel[ii][jj]);
        }
    }
}

__global__ __launch_bounds__(256, 4) void pairwise_kernel(const float* __restrict__ pred,
                                                          const float* __restrict__ tgt) {
    const int b    = blockIdx.x / CHUNKS;
    const int c    = blockIdx.x % CHUNKS;
    const int tid  = threadIdx.x;
    const int slot = tid & 63;
    const int w    = tid >> 5;
    const int q    = w >> 1;                  // warp-uniform class

    const int t0   = c * ROWSPC;
    const int tend = (t0 + ROWSPC < TT) ? (t0 + ROWSPC) : TT;

    float sel[5][5];
    float tot[5];
#pragma unroll
    for (int ii = 0; ii < 5; ii++) {
        tot[ii] = 0.0f;
#pragma unroll
        for (int jj = 0; jj < 5; jj++) sel[ii][jj] = 0.0f;
    }

    switch (q) {
        case 0: pw_body<0, 0>(pred, tgt, b, t0, tend, slot, sel, tot); break;
        case 1: pw_body<1, 0>(pred, tgt, b, t0, tend, slot, sel, tot); break;
        case 2: pw_body<0, 1>(pred, tgt, b, t0, tend, slot, sel, tot); break;
        default: pw_body<1, 1>(pred, tgt, b, t0, tend, slot, sel, tot); break;
    }

    // Full-warp tree reduction of the 30 accumulators -> lane 0.
#pragma unroll
    for (int ii = 0; ii < 5; ii++) {
#pragma unroll
        for (int jj = 0; jj < 5; jj++) {
            float v = sel[ii][jj];
#pragma unroll
            for (int o = 16; o; o >>= 1) v += __shfl_down_sync(FULL, v, o);
            sel[ii][jj] = v;
        }
        float v = tot[ii];
#pragma unroll
        for (int o = 16; o; o >>= 1) v += __shfl_down_sync(FULL, v, o);
        tot[ii] = v;
    }

    __shared__ float s[8][30];
    const int lane = tid & 31;
    if (lane == 0) {
#pragma unroll
        for (int ii = 0; ii < 5; ii++) {
#pragma unroll
            for (int jj = 0; jj < 5; jj++) s[w][ii * 5 + jj] = sel[ii][jj];
            s[w][25 + ii] = tot[ii];
        }
    }
    __syncthreads();

    if (tid < NACC) {
        int qq, idx;
        if (tid < 100) {
            const int i = tid / 10, j = tid % 10;
            const int ih = (i >= 5), jh = (j >= 5);
            qq  = jh * 2 + ih;
            idx = (i % 5) * 5 + (j % 5);
        } else {
            const int i = tid - 100;
            const int ih = (i >= 5);
            qq  = ih;                      // tot kept only by jhalf==0 classes
            idx = 25 + (i % 5);
        }
        g_part[(b * CHUNKS + c) * NACC + tid] =
            (s[2 * qq][idx] + s[2 * qq + 1][idx]) * LN2F;   // lg2 -> ln once
    }
}

// ---------------------------------------------------------------------------
// Kernel 2: Hungarian, 4 BATCHES PER BLOCK (grid=16, 4 warps). Algorithm is
// the frozen r10 warp-JV; packing 4 warps/block concentrates the work on 16
// SMs so I$ cold-start is paid 16x not 64x and warps hide each other's
// REDUX/LDS latency.
// ---------------------------------------------------------------------------
__global__ __launch_bounds__(128) void hungarian_kernel(float* __restrict__ out) {
    __shared__ float s_cost[4][100];
    const int tid  = threadIdx.x;
    const int w    = tid >> 5;
    const int lane = tid & 31;
    const int b    = blockIdx.x * 4 + w;      // one batch per warp

    // Warp-local cost build from chunk partials.
    for (int k = lane; k < 100; k += 32) {
        const int i = k / 10;
        float sl = 0.0f, to = 0.0f;
#pragma unroll
        for (int c = 0; c < CHUNKS; c++) {
            const float* gp = &g_part[(b * CHUNKS + c) * NACC];
            sl += __ldcg(&gp[k]);
            to += __ldcg(&gp[100 + i]);
        }
        s_cost[w][k] = -(to + sl) * (1.0f / (float)TT);
    }
    __syncwarp();

    const bool isCol = (lane >= 1 && lane <= SS);
    const int  cl    = isCol ? (lane - 1) : 0;

    float colv[SS];
#pragma unroll
    for (int i = 0; i < SS; i++) colv[i] = s_cost[w][i * 10 + cl];

    // Warm start: v[j] = min_i colv (lane); u[i] = min_j (colv[i]-v) (uniform).
    float v = 0.0f;
    if (isCol) {
        float mn = colv[0];
#pragma unroll
        for (int i = 1; i < SS; i++) mn = fminf(mn, colv[i]);
        v = mn;
    }
    float uu[SS];
#pragma unroll
    for (int i = 0; i < SS; i++) {
        const float t = isCol ? (colv[i] - v) : FLT_MAX_C;
        uu[i] = dec_f32(__reduce_min_sync(FULL, enc_f32(t)));   // exact (full key)
    }

    // Greedy tight-edge pre-assignment (p64 kept uniform in all lanes).
    u64 p64 = 0ull;
    int way = 0;                       // lane j: alternating-path parent
    unsigned rowdone = 0u;
#pragma unroll
    for (int i = 1; i <= SS; i++) {
        const float red = isCol ? ((colv[i - 1] - v) - uu[i - 1]) : 1.0f;
        const bool  z   = isCol && (nib_get(p64, lane) == 0) && (red == 0.0f);
        const unsigned bal = __ballot_sync(FULL, z);
        if (bal) {
            const int j = __ffs(bal) - 1;
            p64 = nib_set(p64, j, i);                   // uniform update
            rowdone |= 1u << i;
        }
    }

    // Dijkstra per remaining free row: ONE collective (REDUX.MIN) per iter.
    for (int root = 1; root <= SS; root++) {
        if ((rowdone >> root) & 1u) continue;
        p64 = nib_set(p64, 0, root);                    // p[0] = root

        float wv[SS];
#pragma unroll
        for (int i = 0; i < SS; i++)
            wv[i] = isCol ? ((colv[i] - uu[i]) - v) : FLT_MAX_C;

        float minv = FLT_MAX_C;
        unsigned used = 1u;            // virtual column 0
        unsigned rowm = 0u;
        int j0 = 0, i0 = root;

        while (true) {
            rowm |= 1u << i0;

            const bool  active = isCol && !((used >> lane) & 1u);
            const float cur    = sel10(wv, i0 - 1);
            if (active && cur < minv) { minv = cur; way = j0; }

            const unsigned key = active ? ((enc_f32(minv) & 0xFFFFFFE0u) | (unsigned)lane)
                                        : 0xFFFFFFFFu;
            const unsigned m   = __reduce_min_sync(FULL, key);
            const int      j1  = (int)(m & 31u);
            const float delta  = dec_f32(m & 0xFFFFFFE0u);  // <=exact by <32ulp; feasible
            const int   pn     = nib_get(p64, j1);          // uniform ALU, no shfl

            if (lane <= SS) {
                if ((used >> lane) & 1u) v -= delta;
                else                     minv -= delta;
            }
#pragma unroll
            for (int i = 1; i <= SS; i++)
                if ((rowm >> i) & 1u) uu[i - 1] += delta;   // uniform

            used |= 1u << j1;
            j0 = j1;
            if (pn == 0) break;
            i0 = pn;
        }

        // Augment along the alternating path (p64 stays uniform).
        while (j0) {
            const int jprev = __shfl_sync(FULL, way, j0);
            p64 = nib_set(p64, j0, nib_get(p64, jprev));
            j0 = jprev;
        }
    }

    // Matched sum (exact f32 cost entries, f64 accumulate).
    double val = 0.0;
    if (isCol) val = (double)s_cost[w][(nib_get(p64, lane) - 1) * 10 + cl];
#pragma unroll
    for (int o = 16; o; o >>= 1) val += __shfl_down_sync(FULL, val, o);
    if (lane == 0) g_bsum[b] = val;

    // Fused finalize: last warp overall computes the mean.
    __threadfence();
    unsigned t2 = 0;
    if (lane == 0) t2 = atomicAdd(&g_ticket2, 1u);
    t2 = __shfl_sync(FULL, t2, 0);
    if (t2 == BB - 1) {
        if (lane == 0) g_ticket2 = 0;              // reset for graph replay
        __threadfence();
        double x = __ldcg(&g_bsum[lane]) + __ldcg(&g_bsum[lane + 32]);
#pragma unroll
        for (int o = 16; o; o >>= 1) x += __shfl_down_sync(FULL, x, o);
        if (lane == 0) out[0] = (float)(x / (double)(BB * SS));
    }
}

extern "C" void kernel_launch(void* const* d_in, const int* in_sizes, int n_in,
                              void* d_out, int out_size) {
    const float* pred = (const float*)d_in[0];
    const float* tgt  = (const float*)d_in[1];
    pairwise_kernel<<<BB * CHUNKS, 256>>>(pred, tgt);
    hungarian_kernel<<<BB / 4, 128>>>((float*)d_out);
}